// round 9
// baseline (speedup 1.0000x reference)
#include <cuda_runtime.h>
#include <cstdint>

// ---- problem constants ----
#define T_DIM   128
#define C_DIM   64
#define F_DIM   64
#define K_DIM   128          // filters = GEMM M
#define CP      62
#define N_TOTAL 4096
#define BN_EPS  1e-3f

#define NROWS   4            // fused (b,t) rows per CTA -> GEMM N = 256
#define THREADS 256
#define NKC     24           // K chunks of 8 (K = 192)
#define STAGES  8
#define LOOKA   7            // fill lookahead (stages in flight)

// smem: As[24][128][8] floats, then Bs[8][256][8] floats (cp.async ring)
#define A_FLOATS 24576
#define B_FLOATS (STAGES * 256 * 8)     // 16384
#define SMEM_FLOATS (A_FLOATS + B_FLOATS)
#define SMEM_BYTES  (SMEM_FLOATS * 4)   // 163840

// epilogue reuse of the same smem: per-warp [64 cp][pitch 68] floats
#define EPI_PITCH 68
#define EPI_WARP  (64 * EPI_PITCH)      // 4352 floats; x8 warps = 34816 <= 40960

__device__ __forceinline__ uint32_t smem_u32(const void* p) {
    uint32_t a;
    asm("{ .reg .u64 t; cvta.to.shared.u64 t, %1; cvt.u32.u64 %0, t; }" : "=r"(a) : "l"(p));
    return a;
}
__device__ __forceinline__ float tf32r(float v) {
    uint32_t u;
    asm("cvt.rna.tf32.f32 %0, %1;" : "=r"(u) : "f"(v));
    return __uint_as_float(u);
}
__device__ __forceinline__ void cp_async16(uint32_t dst, const void* src, int sz) {
    asm volatile("cp.async.ca.shared.global [%0], [%1], 16, %2;"
                 :: "r"(dst), "l"(src), "r"(sz) : "memory");
}
#define CP_COMMIT() asm volatile("cp.async.commit_group;" ::: "memory")
#define CP_WAIT6()  asm volatile("cp.async.wait_group 6;" ::: "memory")

// Fill one B stage sk (K-chunk index 0..23) via cp.async: raw fp32, linear k.
// Stage layout: Bs[sk&7][n_idx(256)][k(8)], n_idx = row*64 + cp.
__device__ __forceinline__ void fill_stage(uint32_t bs_addr, const float* __restrict__ x,
                                           int n0c, int sk, int tid) {
    const int kh  = sk >> 3;
    const int kw0 = (sk & 7) << 3;
    const int rowt = tid >> 6;
    const int cpt  = tid & 63;
    const int c    = cpt + kh;
    const int c_eff = (c < C_DIM) ? c : 0;
    const int sz    = (c < C_DIM) ? 16 : 0;
    const float* src = x + (size_t)(n0c + rowt) * (C_DIM * F_DIM) + c_eff * F_DIM + kw0;
    const uint32_t dst = bs_addr + (uint32_t)(((sk & 7) * 2048 + tid * 8) * 4);
    cp_async16(dst,      src,     sz);
    cp_async16(dst + 16, src + 4, sz);
}

__global__ __launch_bounds__(THREADS)
void tccnn_mma2_kernel(const float* __restrict__ x,
                       const float* __restrict__ conv_w,
                       const float* __restrict__ conv_b,
                       const float* __restrict__ bn_gamma,
                       const float* __restrict__ bn_beta,
                       const float* __restrict__ bn_mean,
                       const float* __restrict__ bn_var,
                       float* __restrict__ out)
{
    extern __shared__ float smem[];
    float* As = smem;
    float* Bs = smem + A_FLOATS;
    const uint32_t bs_addr = smem_u32(Bs);

    const int tid  = threadIdx.x;
    const int lane = tid & 31;
    const int wid  = tid >> 5;
    const int r    = lane >> 2;        // 0..7
    const int cql  = lane & 3;         // 0..3
    const int m0w  = (wid & 1) * 64;   // warp M origin (2 m-warps)
    const int row  = wid >> 1;         // warp's fused row 0..3 (4 n-warps)
    const int n0c  = blockIdx.x * NROWS;

    // ---- stage A: As[kc][m][8 perm] = tf32(conv_w[kk*128 + m]) ----
    {
        const int m   = tid & 127;
        const int kk0 = (tid >> 7) * 96;
        #pragma unroll 4
        for (int j = 0; j < 96; ++j) {
            const int kk = kk0 + j;
            const float v = tf32r(conv_w[kk * K_DIM + m]);
            const int pos = ((kk & 3) << 1) | ((kk >> 2) & 1);
            As[(kk >> 3) * (K_DIM * 8) + m * 8 + pos] = v;
        }
    }

    // ---- B prologue: stages 0..6 in flight ----
    #pragma unroll
    for (int s = 0; s < LOOKA; ++s) {
        fill_stage(bs_addr, x, n0c, s, tid);
        CP_COMMIT();
    }

    float acc[4][8][4];
    #pragma unroll
    for (int mt = 0; mt < 4; ++mt)
        #pragma unroll
        for (int nt = 0; nt < 8; ++nt)
            #pragma unroll
            for (int q = 0; q < 4; ++q)
                acc[mt][nt][q] = 0.0f;

    // ---- mainloop over 24 K-chunks ----
    #pragma unroll 1
    for (int kc = 0; kc < NKC; ++kc) {
        CP_WAIT6();                    // stage kc complete
        __syncthreads();               // visible to all warps (also covers A on kc=0)

        if (kc + LOOKA < NKC) {
            fill_stage(bs_addr, x, n0c, kc + LOOKA, tid);
            CP_COMMIT();
        } else {
            CP_COMMIT();               // empty group keeps wait_group count uniform
        }

        const float* Ak = As + kc * (K_DIM * 8);
        const float* Bk = Bs + (kc & 7) * 2048 + row * (64 * 8);

        uint32_t a[4][4];
        #pragma unroll
        for (int mt = 0; mt < 4; ++mt) {
            const float2 lo = *(const float2*)(Ak + (m0w + 16 * mt     + r) * 8 + 2 * cql);
            const float2 hi = *(const float2*)(Ak + (m0w + 16 * mt + 8 + r) * 8 + 2 * cql);
            a[mt][0] = __float_as_uint(lo.x);
            a[mt][1] = __float_as_uint(hi.x);
            a[mt][2] = __float_as_uint(lo.y);
            a[mt][3] = __float_as_uint(hi.y);
        }

        #pragma unroll
        for (int nt = 0; nt < 8; ++nt) {
            const float* bp = Bk + (8 * nt + r) * 8;
            const uint32_t b0 = __float_as_uint(bp[cql]);      // k = cql
            const uint32_t b1 = __float_as_uint(bp[cql + 4]);  // k = cql + 4
            #pragma unroll
            for (int mt = 0; mt < 4; ++mt) {
                asm volatile(
                    "mma.sync.aligned.m16n8k8.row.col.f32.tf32.tf32.f32 "
                    "{%0,%1,%2,%3}, {%4,%5,%6,%7}, {%8,%9}, {%0,%1,%2,%3};"
                    : "+f"(acc[mt][nt][0]), "+f"(acc[mt][nt][1]),
                      "+f"(acc[mt][nt][2]), "+f"(acc[mt][nt][3])
                    : "r"(a[mt][0]), "r"(a[mt][1]), "r"(a[mt][2]), "r"(a[mt][3]),
                      "r"(b0), "r"(b1));
            }
        }
    }

    __syncthreads();   // mainloop smem reads done; reuse smem for epilogue buffers

    // ---- epilogue: bias + BN(t) + ReLU -> per-warp smem -> coalesced STG ----
    {
        const int n = n0c + row;
        const int t = n & (T_DIM - 1);
        const float inv = rsqrtf(bn_var[t] + BN_EPS);
        const float s   = bn_gamma[t] * inv;
        const float sh  = bn_beta[t] - bn_mean[t] * s;

        float* buf = smem + wid * EPI_WARP;   // [cp 64][pitch 68]

        float bias_v[4][2];
        #pragma unroll
        for (int mt = 0; mt < 4; ++mt) {
            bias_v[mt][0] = conv_b[m0w + 16 * mt + r];
            bias_v[mt][1] = conv_b[m0w + 16 * mt + 8 + r];
        }

        #pragma unroll
        for (int mt = 0; mt < 4; ++mt) {
            const int ml = 16 * mt + r;       // local m (0..63)
            const int mh = ml + 8;
            #pragma unroll
            for (int nt = 0; nt < 8; ++nt) {
                const int cp0 = 8 * nt + 2 * cql;
                buf[cp0       * EPI_PITCH + ml] = fmaxf((acc[mt][nt][0] + bias_v[mt][0]) * s + sh, 0.f);
                buf[(cp0 + 1) * EPI_PITCH + ml] = fmaxf((acc[mt][nt][1] + bias_v[mt][0]) * s + sh, 0.f);
                buf[cp0       * EPI_PITCH + mh] = fmaxf((acc[mt][nt][2] + bias_v[mt][1]) * s + sh, 0.f);
                buf[(cp0 + 1) * EPI_PITCH + mh] = fmaxf((acc[mt][nt][3] + bias_v[mt][1]) * s + sh, 0.f);
            }
        }
        __syncwarp();

        float* outn = out + (size_t)n * (CP * K_DIM) + m0w;
        const int cph = lane >> 4;            // 0/1
        const int m4  = 4 * (lane & 15);      // 0..60
        #pragma unroll
        for (int it = 0; it < 32; ++it) {
            const int cp = 2 * it + cph;
            if (cp < CP) {
                const float4 v = *(const float4*)(buf + cp * EPI_PITCH + m4);
                *(float4*)(outn + cp * K_DIM + m4) = v;
            }
        }
    }
}

extern "C" void kernel_launch(void* const* d_in, const int* in_sizes, int n_in,
                              void* d_out, int out_size)
{
    const float* x        = (const float*)d_in[0];
    const float* conv_w   = (const float*)d_in[1];
    const float* conv_b   = (const float*)d_in[2];
    const float* bn_gamma = (const float*)d_in[3];
    const float* bn_beta  = (const float*)d_in[4];
    const float* bn_mean  = (const float*)d_in[5];
    const float* bn_var   = (const float*)d_in[6];
    float* out = (float*)d_out;

    cudaFuncSetAttribute(tccnn_mma2_kernel,
                         cudaFuncAttributeMaxDynamicSharedMemorySize, SMEM_BYTES);

    tccnn_mma2_kernel<<<N_TOTAL / NROWS, THREADS, SMEM_BYTES>>>(
        x, conv_w, conv_b, bn_gamma, bn_beta, bn_mean, bn_var, out);
}

// round 11
// speedup vs baseline: 1.2547x; 1.2547x over previous
#include <cuda_runtime.h>
#include <cstdint>

// ---- problem constants ----
#define T_DIM   128
#define C_DIM   64
#define F_DIM   64
#define K_DIM   128          // filters = GEMM M
#define CP      62
#define N_TOTAL 4096
#define BN_EPS  1e-3f

#define NROWS   4            // fused (b,t) rows per CTA -> GEMM N = 256
#define THREADS 512
#define NKC     24           // K chunks of 8 (K = 192)
#define NSTG    12           // stages of 2 kc
#define RING    4            // ring slots (16 KB each)
#define LOOKA   3

// smem: As[24][128][8] floats, then Bs[4][2][256][8] floats
#define A_FLOATS 24576
#define STG_FLOATS 4096                  // 2 kc * 256 n * 8 k
#define B_FLOATS (RING * STG_FLOATS)     // 16384
#define SMEM_BYTES  ((A_FLOATS + B_FLOATS) * 4)   // 163840

// epilogue smem reuse: per-warp [32 cp][pitch 68]
#define EPI_PITCH 68
#define EPI_WARP  (32 * EPI_PITCH)       // 2176 floats; x16 = 34816 <= 40960

__device__ __forceinline__ uint32_t smem_u32(const void* p) {
    uint32_t a;
    asm("{ .reg .u64 t; cvta.to.shared.u64 t, %1; cvt.u32.u64 %0, t; }" : "=r"(a) : "l"(p));
    return a;
}
__device__ __forceinline__ float tf32r(float v) {
    uint32_t u;
    asm("cvt.rna.tf32.f32 %0, %1;" : "=r"(u) : "f"(v));
    return __uint_as_float(u);
}
__device__ __forceinline__ void cp_async16(uint32_t dst, const void* src, int sz) {
    asm volatile("cp.async.ca.shared.global [%0], [%1], 16, %2;"
                 :: "r"(dst), "l"(src), "r"(sz) : "memory");
}
#define CP_COMMIT() asm volatile("cp.async.commit_group;" ::: "memory")
#define CP_WAIT2()  asm volatile("cp.async.wait_group 2;" ::: "memory")

// Fill stage si (2 K-chunks 2si, 2si+1). 512 threads: n = tid>>1, khalf = tid&1.
__device__ __forceinline__ void fill_stage(uint32_t bs_addr, const float* __restrict__ x,
                                           int n0c, int si, int tid) {
    const int n    = tid >> 1;          // 0..255 = row*64 + cp
    const int half = tid & 1;           // k 0-3 / 4-7
    const int row  = n >> 6;
    const int cp   = n & 63;
    const float* xrow = x + (size_t)(n0c + row) * (C_DIM * F_DIM);
    #pragma unroll
    for (int j = 0; j < 2; ++j) {
        const int sk  = 2 * si + j;
        const int kh  = sk >> 3;
        const int kw  = ((sk & 7) << 3) + 4 * half;
        const int c   = cp + kh;
        const int ce  = (c < C_DIM) ? c : 0;
        const int sz  = (c < C_DIM) ? 16 : 0;
        const uint32_t dst = bs_addr
            + (uint32_t)(((si & 3) * STG_FLOATS + j * 2048 + n * 8 + 4 * half) * 4);
        cp_async16(dst, xrow + ce * F_DIM + kw, sz);
    }
}

__global__ __launch_bounds__(THREADS, 1)
void tccnn_mma3_kernel(const float* __restrict__ x,
                       const float* __restrict__ conv_w,
                       const float* __restrict__ conv_b,
                       const float* __restrict__ bn_gamma,
                       const float* __restrict__ bn_beta,
                       const float* __restrict__ bn_mean,
                       const float* __restrict__ bn_var,
                       float* __restrict__ out)
{
    extern __shared__ float smem[];
    float* As = smem;
    float* Bs = smem + A_FLOATS;
    const uint32_t bs_addr = smem_u32(Bs);

    const int tid  = threadIdx.x;
    const int lane = tid & 31;
    const int wid  = tid >> 5;           // 0..15
    const int r    = lane >> 2;          // 0..7
    const int cql  = lane & 3;           // 0..3
    const int m0w  = (wid & 1) * 64;     // M origin: 2 m-warps
    const int nw   = wid >> 1;           // 0..7 n-slice
    const int row  = nw >> 1;            // fused row 0..3
    const int nhalf= (nw & 1) * 32;      // cp origin within row
    const int n0c  = blockIdx.x * NROWS;

    // ---- stage A: As[kc][m][8 perm] = tf32(conv_w[kk*128 + m]) ----
    {
        const int m   = tid & 127;
        const int kk0 = (tid >> 7) * 48;
        #pragma unroll 4
        for (int j = 0; j < 48; ++j) {
            const int kk = kk0 + j;
            const float v = tf32r(conv_w[kk * K_DIM + m]);
            const int pos = ((kk & 3) << 1) | ((kk >> 2) & 1);
            As[(kk >> 3) * (K_DIM * 8) + m * 8 + pos] = v;
        }
    }

    // ---- prologue: stages 0..2 in flight ----
    #pragma unroll
    for (int s = 0; s < LOOKA; ++s) {
        fill_stage(bs_addr, x, n0c, s, tid);
        CP_COMMIT();
    }

    float acc[4][4][4];
    #pragma unroll
    for (int mt = 0; mt < 4; ++mt)
        #pragma unroll
        for (int nt = 0; nt < 4; ++nt)
            #pragma unroll
            for (int q = 0; q < 4; ++q)
                acc[mt][nt][q] = 0.0f;

    // ---- mainloop: 12 stages x 2 kc ----
    #pragma unroll 1
    for (int si = 0; si < NSTG; ++si) {
        CP_WAIT2();                 // stage si landed
        __syncthreads();            // visible to all; also covers A on si=0

        if (si + LOOKA < NSTG)
            fill_stage(bs_addr, x, n0c, si + LOOKA, tid);
        CP_COMMIT();

        #pragma unroll
        for (int j = 0; j < 2; ++j) {
            const int kc = 2 * si + j;
            const float* Ak = As + kc * (K_DIM * 8);
            const float* Bk = Bs + (si & 3) * STG_FLOATS + j * 2048
                            + (row * 64 + nhalf) * 8;

            uint32_t a[4][4];
            #pragma unroll
            for (int mt = 0; mt < 4; ++mt) {
                const float2 lo = *(const float2*)(Ak + (m0w + 16 * mt     + r) * 8 + 2 * cql);
                const float2 hi = *(const float2*)(Ak + (m0w + 16 * mt + 8 + r) * 8 + 2 * cql);
                a[mt][0] = __float_as_uint(lo.x);
                a[mt][1] = __float_as_uint(hi.x);
                a[mt][2] = __float_as_uint(lo.y);
                a[mt][3] = __float_as_uint(hi.y);
            }
            #pragma unroll
            for (int nt = 0; nt < 4; ++nt) {
                const float* bp = Bk + (8 * nt + r) * 8;
                const uint32_t b0 = __float_as_uint(bp[cql]);
                const uint32_t b1 = __float_as_uint(bp[cql + 4]);
                #pragma unroll
                for (int mt = 0; mt < 4; ++mt) {
                    asm volatile(
                        "mma.sync.aligned.m16n8k8.row.col.f32.tf32.tf32.f32 "
                        "{%0,%1,%2,%3}, {%4,%5,%6,%7}, {%8,%9}, {%0,%1,%2,%3};"
                        : "+f"(acc[mt][nt][0]), "+f"(acc[mt][nt][1]),
                          "+f"(acc[mt][nt][2]), "+f"(acc[mt][nt][3])
                        : "r"(a[mt][0]), "r"(a[mt][1]), "r"(a[mt][2]), "r"(a[mt][3]),
                          "r"(b0), "r"(b1));
                }
            }
        }
    }

    __syncthreads();   // all mainloop smem reads done; reuse smem for epilogue

    // ---- epilogue: bias + BN(t) + ReLU -> smem stage -> coalesced STG ----
    {
        const int n = n0c + row;
        const int t = n & (T_DIM - 1);
        const float inv = rsqrtf(bn_var[t] + BN_EPS);
        const float s   = bn_gamma[t] * inv;
        const float sh  = bn_beta[t] - bn_mean[t] * s;

        float* buf = smem + wid * EPI_WARP;   // [32 cp][68]

        #pragma unroll
        for (int mt = 0; mt < 4; ++mt) {
            const int ml = 16 * mt + r;
            const int mh = ml + 8;
            const float bl = conv_b[m0w + ml];
            const float bh = conv_b[m0w + mh];
            #pragma unroll
            for (int nt = 0; nt < 4; ++nt) {
                const int cp0 = 8 * nt + 2 * cql;
                buf[cp0       * EPI_PITCH + ml] = fmaxf((acc[mt][nt][0] + bl) * s + sh, 0.f);
                buf[(cp0 + 1) * EPI_PITCH + ml] = fmaxf((acc[mt][nt][1] + bl) * s + sh, 0.f);
                buf[cp0       * EPI_PITCH + mh] = fmaxf((acc[mt][nt][2] + bh) * s + sh, 0.f);
                buf[(cp0 + 1) * EPI_PITCH + mh] = fmaxf((acc[mt][nt][3] + bh) * s + sh, 0.f);
            }
        }
        __syncwarp();

        float* outn = out + (size_t)n * (CP * K_DIM) + m0w;
        const int cph = lane >> 4;            // 0/1
        const int m4  = 4 * (lane & 15);      // 0..60
        #pragma unroll
        for (int it = 0; it < 16; ++it) {
            const int cp  = 2 * it + cph;     // 0..31 local
            const int cpg = nhalf + cp;       // global cp
            if (cpg < CP) {
                const float4 v = *(const float4*)(buf + cp * EPI_PITCH + m4);
                *(float4*)(outn + cpg * K_DIM + m4) = v;
            }
        }
    }
}

extern "C" void kernel_launch(void* const* d_in, const int* in_sizes, int n_in,
                              void* d_out, int out_size)
{
    const float* x        = (const float*)d_in[0];
    const float* conv_w   = (const float*)d_in[1];
    const float* conv_b   = (const float*)d_in[2];
    const float* bn_gamma = (const float*)d_in[3];
    const float* bn_beta  = (const float*)d_in[4];
    const float* bn_mean  = (const float*)d_in[5];
    const float* bn_var   = (const float*)d_in[6];
    float* out = (float*)d_out;

    cudaFuncSetAttribute(tccnn_mma3_kernel,
                         cudaFuncAttributeMaxDynamicSharedMemorySize, SMEM_BYTES);

    tccnn_mma3_kernel<<<N_TOTAL / NROWS, THREADS, SMEM_BYTES>>>(
        x, conv_w, conv_b, bn_gamma, bn_beta, bn_mean, bn_var, out);
}

// round 12
// speedup vs baseline: 1.2872x; 1.0259x over previous
#include <cuda_runtime.h>
#include <cstdint>

// ---- problem constants ----
#define T_DIM   128
#define C_DIM   64
#define F_DIM   64
#define K_DIM   128          // filters = GEMM M
#define CP      62
#define N_TOTAL 4096
#define BN_EPS  1e-3f

#define NROWS   4            // fused rows per CTA -> GEMM N = 256
#define THREADS 512
#define NKC     24           // K chunks of 8 (K = 192)
#define NSTG    6            // stages of 4 kc
#define RING    3
#define LOOKA   2

// smem: As[24][128][8] floats, then Bs[3][4][256][8] floats
#define A_FLOATS 24576
#define STG_FLOATS 8192                  // 4 kc * 256 n * 8 k
#define B_FLOATS (RING * STG_FLOATS)     // 24576
#define SMEM_BYTES  ((A_FLOATS + B_FLOATS) * 4)   // 196608

// epilogue smem reuse: per-warp [32 cp][pitch 68]
#define EPI_PITCH 68
#define EPI_WARP  (32 * EPI_PITCH)

__device__ __forceinline__ uint32_t smem_u32(const void* p) {
    uint32_t a;
    asm("{ .reg .u64 t; cvta.to.shared.u64 t, %1; cvt.u32.u64 %0, t; }" : "=r"(a) : "l"(p));
    return a;
}
__device__ __forceinline__ float tf32r(float v) {
    uint32_t u;
    asm("cvt.rna.tf32.f32 %0, %1;" : "=r"(u) : "f"(v));
    return __uint_as_float(u);
}
__device__ __forceinline__ void cp_async16(uint32_t dst, const void* src, int sz) {
    asm volatile("cp.async.ca.shared.global [%0], [%1], 16, %2;"
                 :: "r"(dst), "l"(src), "r"(sz) : "memory");
}
#define CP_COMMIT() asm volatile("cp.async.commit_group;" ::: "memory")
#define CP_WAIT1()  asm volatile("cp.async.wait_group 1;" ::: "memory")

// Fill stage fsi (4 K-chunks) into ring slot. 512 threads: n = tid>>1, half = tid&1.
__device__ __forceinline__ void fill_stage(uint32_t bs_addr, const float* __restrict__ x,
                                           int n0c, int fsi, int slot, int tid) {
    const int n    = tid >> 1;          // 0..255 = row*64 + cp
    const int half = tid & 1;           // k 0-3 / 4-7
    const int row  = n >> 6;
    const int cp   = n & 63;
    const float* xrow = x + (size_t)(n0c + row) * (C_DIM * F_DIM);
    #pragma unroll
    for (int j = 0; j < 4; ++j) {
        const int sk  = 4 * fsi + j;
        const int kh  = sk >> 3;
        const int kw  = ((sk & 7) << 3) + 4 * half;
        const int c   = cp + kh;
        const int ce  = (c < C_DIM) ? c : 0;
        const int sz  = (c < C_DIM) ? 16 : 0;
        const uint32_t dst = bs_addr
            + (uint32_t)((slot * STG_FLOATS + j * 2048 + n * 8 + 4 * half) * 4);
        cp_async16(dst, xrow + ce * F_DIM + kw, sz);
    }
}

// Load one kc's B fragments (8 floats) for this warp's n-slice.
__device__ __forceinline__ void load_bfrag(float* bb, const float* bk, int r, int cql) {
    #pragma unroll
    for (int nt = 0; nt < 4; ++nt) {
        const float* bp = bk + (8 * nt + r) * 8;
        bb[2 * nt]     = bp[cql];
        bb[2 * nt + 1] = bp[cql + 4];
    }
}

__global__ __launch_bounds__(THREADS, 1)
void tccnn_mma4_kernel(const float* __restrict__ x,
                       const float* __restrict__ conv_w,
                       const float* __restrict__ conv_b,
                       const float* __restrict__ bn_gamma,
                       const float* __restrict__ bn_beta,
                       const float* __restrict__ bn_mean,
                       const float* __restrict__ bn_var,
                       float* __restrict__ out)
{
    extern __shared__ float smem[];
    float* As = smem;
    float* Bs = smem + A_FLOATS;
    const uint32_t bs_addr = smem_u32(Bs);

    const int tid  = threadIdx.x;
    const int lane = tid & 31;
    const int wid  = tid >> 5;           // 0..15
    const int r    = lane >> 2;          // 0..7
    const int cql  = lane & 3;           // 0..3
    const int m0w  = (wid & 1) * 64;     // M origin: 2 m-warps
    const int nw   = wid >> 1;           // 0..7 n-slice
    const int row  = nw >> 1;            // fused row 0..3
    const int nhalf= (nw & 1) * 32;      // cp origin within row
    const int n0c  = blockIdx.x * NROWS;

    // ---- stage A: As[kc][m][8 perm] = tf32(conv_w[kk*128 + m]) ----
    {
        const int m   = tid & 127;
        const int kk0 = (tid >> 7) * 48;
        #pragma unroll 4
        for (int j = 0; j < 48; ++j) {
            const int kk = kk0 + j;
            const float v = tf32r(conv_w[kk * K_DIM + m]);
            const int pos = ((kk & 3) << 1) | ((kk >> 2) & 1);
            As[(kk >> 3) * (K_DIM * 8) + m * 8 + pos] = v;
        }
    }

    // ---- prologue: stages 0,1 in flight ----
    fill_stage(bs_addr, x, n0c, 0, 0, tid); CP_COMMIT();
    fill_stage(bs_addr, x, n0c, 1, 1, tid); CP_COMMIT();

    float acc[4][4][4];
    #pragma unroll
    for (int mt = 0; mt < 4; ++mt)
        #pragma unroll
        for (int nt = 0; nt < 4; ++nt)
            #pragma unroll
            for (int q = 0; q < 4; ++q)
                acc[mt][nt][q] = 0.0f;

    // ---- mainloop: 6 stages x 4 kc, B frags double-buffered in regs ----
    #pragma unroll 1
    for (int si = 0; si < NSTG; ++si) {
        CP_WAIT1();                 // stage si resident (in-order retirement)
        __syncthreads();            // visible to all; also covers A on si=0

        const int fsi = si + LOOKA;
        if (fsi < NSTG) {
            const int fslot = (fsi >= RING) ? fsi - RING : fsi;
            fill_stage(bs_addr, x, n0c, fsi, fslot, tid);
        }
        CP_COMMIT();

        const int slot = (si >= RING) ? si - RING : si;
        const float* Bst = Bs + slot * STG_FLOATS + (row * 64 + nhalf) * 8;

        float bb[2][8];
        load_bfrag(bb[0], Bst, r, cql);

        #pragma unroll
        for (int j = 0; j < 4; ++j) {
            if (j < 3)
                load_bfrag(bb[(j + 1) & 1], Bst + (j + 1) * 2048, r, cql);

            const float* Ak = As + (4 * si + j) * (K_DIM * 8);
            uint32_t a[4][4];
            #pragma unroll
            for (int mt = 0; mt < 4; ++mt) {
                const float2 lo = *(const float2*)(Ak + (m0w + 16 * mt     + r) * 8 + 2 * cql);
                const float2 hi = *(const float2*)(Ak + (m0w + 16 * mt + 8 + r) * 8 + 2 * cql);
                a[mt][0] = __float_as_uint(lo.x);
                a[mt][1] = __float_as_uint(hi.x);
                a[mt][2] = __float_as_uint(lo.y);
                a[mt][3] = __float_as_uint(hi.y);
            }

            const float* bj = bb[j & 1];
            #pragma unroll
            for (int nt = 0; nt < 4; ++nt) {
                const uint32_t b0 = __float_as_uint(bj[2 * nt]);
                const uint32_t b1 = __float_as_uint(bj[2 * nt + 1]);
                #pragma unroll
                for (int mt = 0; mt < 4; ++mt) {
                    asm volatile(
                        "mma.sync.aligned.m16n8k8.row.col.f32.tf32.tf32.f32 "
                        "{%0,%1,%2,%3}, {%4,%5,%6,%7}, {%8,%9}, {%0,%1,%2,%3};"
                        : "+f"(acc[mt][nt][0]), "+f"(acc[mt][nt][1]),
                          "+f"(acc[mt][nt][2]), "+f"(acc[mt][nt][3])
                        : "r"(a[mt][0]), "r"(a[mt][1]), "r"(a[mt][2]), "r"(a[mt][3]),
                          "r"(b0), "r"(b1));
                }
            }
        }
    }

    __syncthreads();   // mainloop smem reads done; reuse smem for epilogue

    // ---- epilogue: bias + BN(t) + ReLU -> smem stage -> coalesced STG ----
    {
        const int n = n0c + row;
        const int t = n & (T_DIM - 1);
        const float inv = rsqrtf(bn_var[t] + BN_EPS);
        const float s   = bn_gamma[t] * inv;
        const float sh  = bn_beta[t] - bn_mean[t] * s;

        float* buf = smem + wid * EPI_WARP;   // [32 cp][68]

        #pragma unroll
        for (int mt = 0; mt < 4; ++mt) {
            const int ml = 16 * mt + r;
            const int mh = ml + 8;
            const float bl = conv_b[m0w + ml];
            const float bh = conv_b[m0w + mh];
            #pragma unroll
            for (int nt = 0; nt < 4; ++nt) {
                const int cp0 = 8 * nt + 2 * cql;
                buf[cp0       * EPI_PITCH + ml] = fmaxf((acc[mt][nt][0] + bl) * s + sh, 0.f);
                buf[(cp0 + 1) * EPI_PITCH + ml] = fmaxf((acc[mt][nt][1] + bl) * s + sh, 0.f);
                buf[cp0       * EPI_PITCH + mh] = fmaxf((acc[mt][nt][2] + bh) * s + sh, 0.f);
                buf[(cp0 + 1) * EPI_PITCH + mh] = fmaxf((acc[mt][nt][3] + bh) * s + sh, 0.f);
            }
        }
        __syncwarp();

        float* outn = out + (size_t)n * (CP * K_DIM) + m0w;
        const int cph = lane >> 4;            // 0/1
        const int m4  = 4 * (lane & 15);      // 0..60
        #pragma unroll
        for (int it = 0; it < 16; ++it) {
            const int cp  = 2 * it + cph;     // local 0..31
            const int cpg = nhalf + cp;
            if (cpg < CP) {
                const float4 v = *(const float4*)(buf + cp * EPI_PITCH + m4);
                *(float4*)(outn + cpg * K_DIM + m4) = v;
            }
        }
    }
}

extern "C" void kernel_launch(void* const* d_in, const int* in_sizes, int n_in,
                              void* d_out, int out_size)
{
    const float* x        = (const float*)d_in[0];
    const float* conv_w   = (const float*)d_in[1];
    const float* conv_b   = (const float*)d_in[2];
    const float* bn_gamma = (const float*)d_in[3];
    const float* bn_beta  = (const float*)d_in[4];
    const float* bn_mean  = (const float*)d_in[5];
    const float* bn_var   = (const float*)d_in[6];
    float* out = (float*)d_out;

    cudaFuncSetAttribute(tccnn_mma4_kernel,
                         cudaFuncAttributeMaxDynamicSharedMemorySize, SMEM_BYTES);

    tccnn_mma4_kernel<<<N_TOTAL / NROWS, THREADS, SMEM_BYTES>>>(
        x, conv_w, conv_b, bn_gamma, bn_beta, bn_mean, bn_var, out);
}